// round 6
// baseline (speedup 1.0000x reference)
#include <cuda_runtime.h>
#include <cuda_bf16.h>
#include <cstdint>

#define NN 100000
#define NE 1200000
#define FEAT4 16           // 64 floats = 16 float4 per node
#define NCLS 40
#define SCAN_NB 391        // ceil(100000/256)

// ---------------- device scratch (no allocs allowed) ----------------
__device__ int    g_src[NE];
__device__ int    g_dst[NE];
__device__ int    g_cnt[NN];
__device__ int    g_rowptr[NN + 1];
__device__ int    g_fill[NN];
__device__ int    g_bsum[512];
__device__ float  g_dinv[NN];
__device__ int2   g_csr[NE];          // {src, bitcast(weight)} grouped by dst
__device__ float4 g_hop1[NN * FEAT4];
__device__ float4 g_hop2[NN * FEAT4];
__device__ float4 g_hop3[NN * FEAT4];
__device__ float4 g_h1[NN * FEAT4];
__device__ float4 g_h2[NN * FEAT4];
__device__ int    g_is64;

// ---------------- dtype detection (int64 vs int32 edge_index) -------
__global__ void k_detect(const long long* p) {
    if (blockIdx.x == 0 && threadIdx.x == 0) {
        int ok = 1;
        #pragma unroll 1
        for (int i = 0; i < 64; i++) {
            long long v = p[i * 997];
            if (v < 0 || v >= NN) { ok = 0; break; }
        }
        g_is64 = ok;
    }
}

__global__ void k_convert(const void* edges) {
    int e = blockIdx.x * blockDim.x + threadIdx.x;
    if (e >= NE) return;
    if (g_is64) {
        const long long* p = (const long long*)edges;
        g_src[e] = (int)p[e];
        g_dst[e] = (int)p[e + NE];
    } else {
        const int* p = (const int*)edges;
        g_src[e] = p[e];
        g_dst[e] = p[e + NE];
    }
}

// ---------------- degree histogram + dinv ---------------------------
__global__ void k_hist() {
    int e = blockIdx.x * blockDim.x + threadIdx.x;
    if (e < NE) atomicAdd(&g_cnt[g_dst[e]], 1);
}

__global__ void k_dinv() {
    int n = blockIdx.x * blockDim.x + threadIdx.x;
    if (n < NN) {
        float d = (float)g_cnt[n];
        g_dinv[n] = (d > 0.f) ? rsqrtf(fmaxf(d, 1.f)) : 0.f;
    }
}

// ---------------- exclusive scan of g_cnt -> g_rowptr ---------------
__global__ void k_scan1() {
    __shared__ int sh[2][256];
    int tid = threadIdx.x;
    int gid = blockIdx.x * 256 + tid;
    int v = (gid < NN) ? g_cnt[gid] : 0;
    sh[0][tid] = v;
    __syncthreads();
    int cur = 0;
    #pragma unroll
    for (int off = 1; off < 256; off <<= 1) {
        int a = sh[cur][tid];
        if (tid >= off) a += sh[cur][tid - off];
        sh[cur ^ 1][tid] = a;
        cur ^= 1;
        __syncthreads();
    }
    int incl = sh[cur][tid];
    if (gid <= NN) g_rowptr[gid] = incl - v;
    if (tid == 255) g_bsum[blockIdx.x] = incl;
}

__global__ void k_scan2() {
    __shared__ int sh[2][512];
    int tid = threadIdx.x;
    int v = (tid < SCAN_NB) ? g_bsum[tid] : 0;
    sh[0][tid] = v;
    __syncthreads();
    int cur = 0;
    #pragma unroll
    for (int off = 1; off < 512; off <<= 1) {
        int a = sh[cur][tid];
        if (tid >= off) a += sh[cur][tid - off];
        sh[cur ^ 1][tid] = a;
        cur ^= 1;
        __syncthreads();
    }
    if (tid < SCAN_NB) g_bsum[tid] = sh[cur][tid] - v;
}

__global__ void k_scan3() {
    int gid = blockIdx.x * 256 + threadIdx.x;
    if (gid < NN) g_rowptr[gid] += g_bsum[gid >> 8];
    if (gid == 0) g_rowptr[NN] = NE;
}

// ---------------- CSR fill (weight fused) ---------------------------
__global__ void k_fill() {
    int e = blockIdx.x * blockDim.x + threadIdx.x;
    if (e >= NE) return;
    int s = g_src[e];
    int d = g_dst[e];
    int pos = g_rowptr[d] + atomicAdd(&g_fill[d], 1);
    float w = g_dinv[s] * g_dinv[d];
    g_csr[pos] = make_int2(s, __float_as_int(w));
}

// ---------------- SpMM (CSR pull, no atomics) -----------------------
__global__ void __launch_bounds__(256) k_spmm_csr(
    const float4* __restrict__ feat, float4* __restrict__ out)
{
    int gid = blockIdx.x * blockDim.x + threadIdx.x;
    if (gid >= NN * 16) return;
    int node = gid >> 4;
    int q    = gid & 15;
    int beg = g_rowptr[node];
    int end = g_rowptr[node + 1];
    float4 acc = make_float4(0.f, 0.f, 0.f, 0.f);
    for (int i = beg; i < end; i++) {
        int2 sw = __ldg(&g_csr[i]);
        float w = __int_as_float(sw.y);
        float4 v = __ldg(&feat[sw.x * FEAT4 + q]);
        acc.x += w * v.x; acc.y += w * v.y;
        acc.z += w * v.z; acc.w += w * v.w;
    }
    out[node * FEAT4 + q] = acc;
}

// ====================================================================
// HMMA tf32 split-3 GEMM, hi/lo precomputed at SMEM-fill time.
// A tile: float2[64][132]  (.x=hi, .y=lo)   132 % 16 == 4 -> LDS.64 ok
// W tile: float2[64][68]                     68 % 16 == 4 -> LDS.64 ok
// ====================================================================
#define AP2 132
#define WP2 68
#define W2OFF (64 * AP2)                       // float2 index of W tile
#define GEMM_SMEM ((64 * AP2 + 64 * WP2) * 8)  // 102400 bytes

__device__ __forceinline__ float tf32f(float x) {
    float r;
    asm("cvt.rna.tf32.f32 %0, %1;" : "=f"(r) : "f"(x));
    return r;
}

__device__ __forceinline__ float2 split2(float x) {
    float hi = tf32f(x);
    return make_float2(hi, tf32f(x - hi));
}

__device__ __forceinline__ void mma_t(float* c, const uint32_t* a,
                                      uint32_t b0, uint32_t b1) {
    asm volatile(
        "mma.sync.aligned.m16n8k8.row.col.f32.tf32.tf32.f32 "
        "{%0,%1,%2,%3}, {%4,%5,%6,%7}, {%8,%9}, {%0,%1,%2,%3};"
        : "+f"(c[0]), "+f"(c[1]), "+f"(c[2]), "+f"(c[3])
        : "r"(a[0]), "r"(a[1]), "r"(a[2]), "r"(a[3]), "r"(b0), "r"(b1));
}

__global__ void __launch_bounds__(128) k_gemm_mma(
    const float4* __restrict__ A0, const float4* __restrict__ A1,
    const float4* __restrict__ A2, const float4* __restrict__ A3,
    const float* __restrict__ W, const float* __restrict__ b,
    float* __restrict__ out, int relu)
{
    extern __shared__ float2 sh2[];            // A tile then W tile

    const int tid  = threadIdx.x;
    const int lane = tid & 31;
    const int w    = tid >> 5;     // warp 0..3 -> rows w*32..w*32+31
    const int g    = lane >> 2;    // group 0..7
    const int tig  = lane & 3;     // 0..3
    const int nb   = blockIdx.x * 128;

    float acc[2][8][4];
    #pragma unroll
    for (int mt = 0; mt < 2; mt++)
        #pragma unroll
        for (int nt = 0; nt < 8; nt++)
            #pragma unroll
            for (int i = 0; i < 4; i++) acc[mt][nt][i] = 0.f;

    #pragma unroll 1
    for (int c = 0; c < 4; c++) {
        const float4* Ap = (c == 0) ? A0 : (c == 1) ? A1 : (c == 2) ? A2 : A3;
        if (c) __syncthreads();

        // ---- fill A tile (thread = node column), split once ----
        {
            int node = nb + tid;
            const float4* row = Ap + (size_t)node * FEAT4;
            #pragma unroll
            for (int j = 0; j < 16; j++) {
                float4 v = (node < NN) ? __ldg(&row[j]) : make_float4(0, 0, 0, 0);
                sh2[(j * 4 + 0) * AP2 + tid] = split2(v.x);
                sh2[(j * 4 + 1) * AP2 + tid] = split2(v.y);
                sh2[(j * 4 + 2) * AP2 + tid] = split2(v.z);
                sh2[(j * 4 + 3) * AP2 + tid] = split2(v.w);
            }
        }
        // ---- fill W tile (64x64 of [256,64] row-major), split once ----
        #pragma unroll
        for (int t = 0; t < 32; t++) {
            int idx = t * 128 + tid;
            int k = idx >> 6, n = idx & 63;
            sh2[W2OFF + k * WP2 + n] = split2(__ldg(&W[(c * 64 + k) * 64 + n]));
        }
        __syncthreads();

        #pragma unroll
        for (int ks = 0; ks < 8; ks++) {
            int k0 = ks * 8;
            // A fragments: one LDS.64 gives hi+lo
            uint32_t ahi[2][4], alo[2][4];
            #pragma unroll
            for (int mt = 0; mt < 2; mt++) {
                int mb = w * 32 + mt * 16;
                float2 f0 = sh2[(k0 + tig) * AP2 + mb + g];
                float2 f1 = sh2[(k0 + tig) * AP2 + mb + 8 + g];
                float2 f2 = sh2[(k0 + 4 + tig) * AP2 + mb + g];
                float2 f3 = sh2[(k0 + 4 + tig) * AP2 + mb + 8 + g];
                ahi[mt][0] = __float_as_uint(f0.x); alo[mt][0] = __float_as_uint(f0.y);
                ahi[mt][1] = __float_as_uint(f1.x); alo[mt][1] = __float_as_uint(f1.y);
                ahi[mt][2] = __float_as_uint(f2.x); alo[mt][2] = __float_as_uint(f2.y);
                ahi[mt][3] = __float_as_uint(f3.x); alo[mt][3] = __float_as_uint(f3.y);
            }
            #pragma unroll
            for (int nt = 0; nt < 8; nt++) {
                float2 w0 = sh2[W2OFF + (k0 + tig) * WP2 + nt * 8 + g];
                float2 w1 = sh2[W2OFF + (k0 + 4 + tig) * WP2 + nt * 8 + g];
                uint32_t bhi0 = __float_as_uint(w0.x), blo0 = __float_as_uint(w0.y);
                uint32_t bhi1 = __float_as_uint(w1.x), blo1 = __float_as_uint(w1.y);
                #pragma unroll
                for (int mt = 0; mt < 2; mt++) {
                    mma_t(acc[mt][nt], ahi[mt], bhi0, bhi1);
                    mma_t(acc[mt][nt], ahi[mt], blo0, blo1);
                    mma_t(acc[mt][nt], alo[mt], bhi0, bhi1);
                }
            }
        }
    }

    // ---- epilogue: c0,c1 at (row g, col 2tig), c2,c3 at (row g+8) ----
    #pragma unroll
    for (int mt = 0; mt < 2; mt++) {
        int row0 = nb + w * 32 + mt * 16 + g;
        int row1 = row0 + 8;
        #pragma unroll
        for (int nt = 0; nt < 8; nt++) {
            int col = nt * 8 + 2 * tig;
            float b0 = __ldg(&b[col]), b1 = __ldg(&b[col + 1]);
            float v0 = acc[mt][nt][0] + b0, v1 = acc[mt][nt][1] + b1;
            float v2 = acc[mt][nt][2] + b0, v3 = acc[mt][nt][3] + b1;
            if (relu) {
                v0 = fmaxf(v0, 0.f); v1 = fmaxf(v1, 0.f);
                v2 = fmaxf(v2, 0.f); v3 = fmaxf(v3, 0.f);
            }
            if (row0 < NN) *(float2*)(out + (size_t)row0 * 64 + col) = make_float2(v0, v1);
            if (row1 < NN) *(float2*)(out + (size_t)row1 * 64 + col) = make_float2(v2, v3);
        }
    }
}

// ---------------- classifier: [N,64] @ Wc[64,40] + bc ---------------
__global__ void k_classifier(const float* __restrict__ h,
                             const float* __restrict__ Wc,
                             const float* __restrict__ bc,
                             float* __restrict__ out)
{
    __shared__ float Ws[64 * NCLS];
    __shared__ float bs[NCLS];
    for (int i = threadIdx.x; i < 64 * NCLS; i += blockDim.x) Ws[i] = Wc[i];
    for (int i = threadIdx.x; i < NCLS; i += blockDim.x) bs[i] = bc[i];
    __syncthreads();

    int gid = blockIdx.x * blockDim.x + threadIdx.x;
    if (gid >= NN * NCLS) return;
    int n = gid / NCLS;
    int c = gid % NCLS;
    const float* row = h + (size_t)n * 64;
    float acc = bs[c];
    #pragma unroll
    for (int i = 0; i < 64; i++) acc += row[i] * Ws[i * NCLS + c];
    out[gid] = acc;
}

// ---------------- launch ---------------------------------------------
extern "C" void kernel_launch(void* const* d_in, const int* in_sizes, int n_in,
                              void* d_out, int out_size)
{
    const float* x  = (const float*)d_in[0];
    const void*  ei = d_in[1];
    const float* W1 = (const float*)d_in[2];
    const float* b1 = (const float*)d_in[3];
    const float* W2 = (const float*)d_in[4];
    const float* b2 = (const float*)d_in[5];
    const float* Wc = (const float*)d_in[6];
    const float* bc = (const float*)d_in[7];
    float* out = (float*)d_out;

    void* tmp;
    cudaGetSymbolAddress(&tmp, g_cnt);  int*    p_cnt  = (int*)tmp;
    cudaGetSymbolAddress(&tmp, g_fill); int*    p_fill = (int*)tmp;
    cudaGetSymbolAddress(&tmp, g_hop1); float4* p_hop1 = (float4*)tmp;
    cudaGetSymbolAddress(&tmp, g_hop2); float4* p_hop2 = (float4*)tmp;
    cudaGetSymbolAddress(&tmp, g_hop3); float4* p_hop3 = (float4*)tmp;
    cudaGetSymbolAddress(&tmp, g_h1);   float4* p_h1   = (float4*)tmp;
    cudaGetSymbolAddress(&tmp, g_h2);   float4* p_h2   = (float4*)tmp;

    cudaFuncSetAttribute(k_gemm_mma, cudaFuncAttributeMaxDynamicSharedMemorySize,
                         GEMM_SMEM);

    const int EB = (NE + 255) / 256;
    const int SB = (NN * 16 + 255) / 256;
    const int NB = (NN + 255) / 256;
    const int GB = (NN + 127) / 128;
    const int CB = (NN * NCLS + 255) / 256;

    // ---- CSR build ----
    k_detect<<<1, 32>>>((const long long*)ei);
    k_convert<<<EB, 256>>>(ei);
    cudaMemsetAsync(p_cnt, 0, NN * sizeof(int));
    cudaMemsetAsync(p_fill, 0, NN * sizeof(int));
    k_hist<<<EB, 256>>>();
    k_dinv<<<NB, 256>>>();
    k_scan1<<<SCAN_NB, 256>>>();
    k_scan2<<<1, 512>>>();
    k_scan3<<<SCAN_NB, 256>>>();
    k_fill<<<EB, 256>>>();

    // ---- layer 1 ----
    k_spmm_csr<<<SB, 256>>>((const float4*)x, p_hop1);
    k_spmm_csr<<<SB, 256>>>(p_hop1, p_hop2);
    k_spmm_csr<<<SB, 256>>>(p_hop2, p_hop3);
    k_gemm_mma<<<GB, 128, GEMM_SMEM>>>((const float4*)x, p_hop1, p_hop2, p_hop3,
                                       W1, b1, (float*)p_h1, 1);

    // ---- layer 2 ----
    k_spmm_csr<<<SB, 256>>>(p_h1, p_hop1);
    k_spmm_csr<<<SB, 256>>>(p_hop1, p_hop2);
    k_spmm_csr<<<SB, 256>>>(p_hop2, p_hop3);
    k_gemm_mma<<<GB, 128, GEMM_SMEM>>>(p_h1, p_hop1, p_hop2, p_hop3,
                                       W2, b2, (float*)p_h2, 1);

    // ---- classifier ----
    k_classifier<<<CB, 256>>>((const float*)p_h2, Wc, bc, out);
}

// round 10
// speedup vs baseline: 1.2185x; 1.2185x over previous
#include <cuda_runtime.h>
#include <cuda_bf16.h>
#include <cstdint>

#define NN 100000
#define NE 1200000
#define FEAT4 16           // 64 floats = 16 float4 per node
#define NCLS 40
#define SCAN_NB 391        // ceil(100000/256)

// ---------------- device scratch (no allocs allowed) ----------------
__device__ int    g_src[NE];
__device__ int    g_dst[NE];
__device__ int    g_cnt[NN];
__device__ int    g_rowptr[NN + 1];
__device__ int    g_fill[NN];
__device__ int    g_bsum[512];
__device__ float  g_dinv[NN];
__device__ int2   g_csr[NE];          // {src, bitcast(weight)} grouped by dst
__device__ float4 g_hop1[NN * FEAT4];
__device__ float4 g_hop2[NN * FEAT4];
__device__ float4 g_hop3[NN * FEAT4];
__device__ float4 g_h1[NN * FEAT4];
__device__ float4 g_h2[NN * FEAT4];
__device__ int    g_is64;

// ---------------- dtype detection (int64 vs int32 edge_index) -------
__global__ void k_detect(const long long* p) {
    if (blockIdx.x == 0 && threadIdx.x == 0) {
        int ok = 1;
        #pragma unroll 1
        for (int i = 0; i < 64; i++) {
            long long v = p[i * 997];
            if (v < 0 || v >= NN) { ok = 0; break; }
        }
        g_is64 = ok;
    }
}

__global__ void k_convert(const void* edges) {
    int e = blockIdx.x * blockDim.x + threadIdx.x;
    if (e >= NE) return;
    if (g_is64) {
        const long long* p = (const long long*)edges;
        g_src[e] = (int)p[e];
        g_dst[e] = (int)p[e + NE];
    } else {
        const int* p = (const int*)edges;
        g_src[e] = p[e];
        g_dst[e] = p[e + NE];
    }
}

// ---------------- degree histogram + dinv ---------------------------
__global__ void k_hist() {
    int e = blockIdx.x * blockDim.x + threadIdx.x;
    if (e < NE) atomicAdd(&g_cnt[g_dst[e]], 1);
}

__global__ void k_dinv() {
    int n = blockIdx.x * blockDim.x + threadIdx.x;
    if (n < NN) {
        float d = (float)g_cnt[n];
        g_dinv[n] = (d > 0.f) ? rsqrtf(fmaxf(d, 1.f)) : 0.f;
    }
}

// ---------------- exclusive scan of g_cnt -> g_rowptr ---------------
__global__ void k_scan1() {
    __shared__ int sh[2][256];
    int tid = threadIdx.x;
    int gid = blockIdx.x * 256 + tid;
    int v = (gid < NN) ? g_cnt[gid] : 0;
    sh[0][tid] = v;
    __syncthreads();
    int cur = 0;
    #pragma unroll
    for (int off = 1; off < 256; off <<= 1) {
        int a = sh[cur][tid];
        if (tid >= off) a += sh[cur][tid - off];
        sh[cur ^ 1][tid] = a;
        cur ^= 1;
        __syncthreads();
    }
    int incl = sh[cur][tid];
    if (gid <= NN) g_rowptr[gid] = incl - v;
    if (tid == 255) g_bsum[blockIdx.x] = incl;
}

__global__ void k_scan2() {
    __shared__ int sh[2][512];
    int tid = threadIdx.x;
    int v = (tid < SCAN_NB) ? g_bsum[tid] : 0;
    sh[0][tid] = v;
    __syncthreads();
    int cur = 0;
    #pragma unroll
    for (int off = 1; off < 512; off <<= 1) {
        int a = sh[cur][tid];
        if (tid >= off) a += sh[cur][tid - off];
        sh[cur ^ 1][tid] = a;
        cur ^= 1;
        __syncthreads();
    }
    if (tid < SCAN_NB) g_bsum[tid] = sh[cur][tid] - v;
}

__global__ void k_scan3() {
    int gid = blockIdx.x * 256 + threadIdx.x;
    if (gid < NN) g_rowptr[gid] += g_bsum[gid >> 8];
    if (gid == 0) g_rowptr[NN] = NE;
}

// ---------------- CSR fill (weight fused) ---------------------------
__global__ void k_fill() {
    int e = blockIdx.x * blockDim.x + threadIdx.x;
    if (e >= NE) return;
    int s = g_src[e];
    int d = g_dst[e];
    int pos = g_rowptr[d] + atomicAdd(&g_fill[d], 1);
    float w = g_dinv[s] * g_dinv[d];
    g_csr[pos] = make_int2(s, __float_as_int(w));
}

// ---------------- SpMM (CSR pull, no atomics) -----------------------
__global__ void __launch_bounds__(256) k_spmm_csr(
    const float4* __restrict__ feat, float4* __restrict__ out)
{
    int gid = blockIdx.x * blockDim.x + threadIdx.x;
    if (gid >= NN * 16) return;
    int node = gid >> 4;
    int q    = gid & 15;
    int beg = g_rowptr[node];
    int end = g_rowptr[node + 1];
    float4 acc = make_float4(0.f, 0.f, 0.f, 0.f);
    for (int i = beg; i < end; i++) {
        int2 sw = __ldg(&g_csr[i]);
        float w = __int_as_float(sw.y);
        float4 v = __ldg(&feat[sw.x * FEAT4 + q]);
        acc.x += w * v.x; acc.y += w * v.y;
        acc.z += w * v.z; acc.w += w * v.w;
    }
    out[node * FEAT4 + q] = acc;
}

// ====================================================================
// HMMA bf16 split-2 GEMM: out[128-tile,64] = concat(hops)[*,256] @ W + b
// hi/lo bf16 tiles precomputed at fill; mma.m16n8k16.bf16, 3 MMAs/term.
// Tiles: Ahi/Alo bf16[128][72] (pitch 72 -> frag bank (4g+tig)%32, clean),
//        Whi/Wlo bf16[64][72] ([n][k] layout for col-major B frags).
// ====================================================================
#define APITCH 72                    // bf16 elems per A row
#define A_SZ   (128 * APITCH)        // 9216 bf16
#define W_SZ   (64 * APITCH)         // 4608 bf16
#define OFF_ALO A_SZ
#define OFF_WHI (2 * A_SZ)
#define OFF_WLO (2 * A_SZ + W_SZ)
#define GEMM_SMEM ((2 * A_SZ + 2 * W_SZ) * 2)   // 55296 bytes -> 4 CTAs/SM

__device__ __forceinline__ void bsplit(float x, __nv_bfloat16& h, __nv_bfloat16& l) {
    h = __float2bfloat16(x);
    l = __float2bfloat16(x - __bfloat162float(h));
}

__device__ __forceinline__ void mma_bf16(float* c, const uint32_t* a,
                                         uint32_t b0, uint32_t b1) {
    asm volatile(
        "mma.sync.aligned.m16n8k16.row.col.f32.bf16.bf16.f32 "
        "{%0,%1,%2,%3}, {%4,%5,%6,%7}, {%8,%9}, {%0,%1,%2,%3};"
        : "+f"(c[0]), "+f"(c[1]), "+f"(c[2]), "+f"(c[3])
        : "r"(a[0]), "r"(a[1]), "r"(a[2]), "r"(a[3]), "r"(b0), "r"(b1));
}

__global__ void __launch_bounds__(128) k_gemm_mma(
    const float4* __restrict__ A0, const float4* __restrict__ A1,
    const float4* __restrict__ A2, const float4* __restrict__ A3,
    const float* __restrict__ W, const float* __restrict__ b,
    float* __restrict__ out, int relu)
{
    extern __shared__ __nv_bfloat16 shb[];
    __nv_bfloat16* Ahi = shb;
    __nv_bfloat16* Alo = shb + OFF_ALO;
    __nv_bfloat16* Whi = shb + OFF_WHI;
    __nv_bfloat16* Wlo = shb + OFF_WLO;
    const uint32_t* A32h = (const uint32_t*)Ahi;
    const uint32_t* A32l = (const uint32_t*)Alo;
    const uint32_t* W32h = (const uint32_t*)Whi;
    const uint32_t* W32l = (const uint32_t*)Wlo;

    const int tid  = threadIdx.x;
    const int lane = tid & 31;
    const int w    = tid >> 5;     // warp 0..3 -> rows w*32..w*32+31
    const int g    = lane >> 2;    // group 0..7
    const int tig  = lane & 3;     // 0..3
    const int nb   = blockIdx.x * 128;

    float acc[2][8][4];
    #pragma unroll
    for (int mt = 0; mt < 2; mt++)
        #pragma unroll
        for (int nt = 0; nt < 8; nt++)
            #pragma unroll
            for (int i = 0; i < 4; i++) acc[mt][nt][i] = 0.f;

    #pragma unroll 1
    for (int c = 0; c < 4; c++) {
        const float4* Ap = (c == 0) ? A0 : (c == 1) ? A1 : (c == 2) ? A2 : A3;
        if (c) __syncthreads();

        // ---- fill A tiles: thread = row (node), k contiguous ----
        {
            int node = nb + tid;
            const float4* row = Ap + (size_t)node * FEAT4;
            #pragma unroll
            for (int j = 0; j < 16; j++) {          // k = 4j..4j+3
                float4 v = (node < NN) ? __ldg(&row[j]) : make_float4(0, 0, 0, 0);
                __nv_bfloat16 h0, h1, h2, h3, l0, l1, l2, l3;
                bsplit(v.x, h0, l0); bsplit(v.y, h1, l1);
                bsplit(v.z, h2, l2); bsplit(v.w, h3, l3);
                int base = tid * APITCH + j * 4;
                *(__nv_bfloat162*)(Ahi + base)     = __nv_bfloat162(h0, h1);
                *(__nv_bfloat162*)(Ahi + base + 2) = __nv_bfloat162(h2, h3);
                *(__nv_bfloat162*)(Alo + base)     = __nv_bfloat162(l0, l1);
                *(__nv_bfloat162*)(Alo + base + 2) = __nv_bfloat162(l2, l3);
            }
        }
        // ---- fill W tiles as [n][k]: thread = (n, k-half) ----
        {
            int n    = tid & 63;
            int half = tid >> 6;                    // 0/1 -> k 0..31 / 32..63
            #pragma unroll
            for (int jj = 0; jj < 8; jj++) {
                int k0 = half * 32 + jj * 4;
                float w0 = __ldg(&W[(c * 64 + k0 + 0) * 64 + n]);
                float w1 = __ldg(&W[(c * 64 + k0 + 1) * 64 + n]);
                float w2 = __ldg(&W[(c * 64 + k0 + 2) * 64 + n]);
                float w3 = __ldg(&W[(c * 64 + k0 + 3) * 64 + n]);
                __nv_bfloat16 h0, h1, h2, h3, l0, l1, l2, l3;
                bsplit(w0, h0, l0); bsplit(w1, h1, l1);
                bsplit(w2, h2, l2); bsplit(w3, h3, l3);
                int base = n * APITCH + k0;
                *(__nv_bfloat162*)(Whi + base)     = __nv_bfloat162(h0, h1);
                *(__nv_bfloat162*)(Whi + base + 2) = __nv_bfloat162(h2, h3);
                *(__nv_bfloat162*)(Wlo + base)     = __nv_bfloat162(l0, l1);
                *(__nv_bfloat162*)(Wlo + base + 2) = __nv_bfloat162(l2, l3);
            }
        }
        __syncthreads();

        // ---- 4 k16-steps; fragments loaded as packed bf16x2 words ----
        #pragma unroll
        for (int ks = 0; ks < 4; ks++) {
            int kw = ks * 8 + tig;                  // word offset within row
            uint32_t ahi[2][4], alo[2][4];
            #pragma unroll
            for (int mt = 0; mt < 2; mt++) {
                int r0 = (w * 32 + mt * 16 + g) * (APITCH / 2) + kw;
                int r1 = r0 + 8 * (APITCH / 2);
                ahi[mt][0] = A32h[r0]; ahi[mt][1] = A32h[r1];
                ahi[mt][2] = A32h[r0 + 4]; ahi[mt][3] = A32h[r1 + 4];
                alo[mt][0] = A32l[r0]; alo[mt][1] = A32l[r1];
                alo[mt][2] = A32l[r0 + 4]; alo[mt][3] = A32l[r1 + 4];
            }
            #pragma unroll
            for (int nt = 0; nt < 8; nt++) {
                int bw = (nt * 8 + g) * (APITCH / 2) + kw;
                uint32_t bh0 = W32h[bw], bh1 = W32h[bw + 4];
                uint32_t bl0 = W32l[bw], bl1 = W32l[bw + 4];
                #pragma unroll
                for (int mt = 0; mt < 2; mt++) {
                    mma_bf16(acc[mt][nt], ahi[mt], bh0, bh1);
                    mma_bf16(acc[mt][nt], ahi[mt], bl0, bl1);
                    mma_bf16(acc[mt][nt], alo[mt], bh0, bh1);
                }
            }
        }
    }

    // ---- epilogue: c0,c1 at (row g, col 2tig), c2,c3 at (row g+8) ----
    #pragma unroll
    for (int mt = 0; mt < 2; mt++) {
        int row0 = nb + w * 32 + mt * 16 + g;
        int row1 = row0 + 8;
        #pragma unroll
        for (int nt = 0; nt < 8; nt++) {
            int col = nt * 8 + 2 * tig;
            float b0 = __ldg(&b[col]), b1 = __ldg(&b[col + 1]);
            float v0 = acc[mt][nt][0] + b0, v1 = acc[mt][nt][1] + b1;
            float v2 = acc[mt][nt][2] + b0, v3 = acc[mt][nt][3] + b1;
            if (relu) {
                v0 = fmaxf(v0, 0.f); v1 = fmaxf(v1, 0.f);
                v2 = fmaxf(v2, 0.f); v3 = fmaxf(v3, 0.f);
            }
            if (row0 < NN) *(float2*)(out + (size_t)row0 * 64 + col) = make_float2(v0, v1);
            if (row1 < NN) *(float2*)(out + (size_t)row1 * 64 + col) = make_float2(v2, v3);
        }
    }
}

// ---------------- classifier: [N,64] @ Wc[64,40] + bc ---------------
__global__ void k_classifier(const float* __restrict__ h,
                             const float* __restrict__ Wc,
                             const float* __restrict__ bc,
                             float* __restrict__ out)
{
    __shared__ float Ws[64 * NCLS];
    __shared__ float bs[NCLS];
    for (int i = threadIdx.x; i < 64 * NCLS; i += blockDim.x) Ws[i] = Wc[i];
    for (int i = threadIdx.x; i < NCLS; i += blockDim.x) bs[i] = bc[i];
    __syncthreads();

    int gid = blockIdx.x * blockDim.x + threadIdx.x;
    if (gid >= NN * NCLS) return;
    int n = gid / NCLS;
    int c = gid % NCLS;
    const float* row = h + (size_t)n * 64;
    float acc = bs[c];
    #pragma unroll
    for (int i = 0; i < 64; i++) acc += row[i] * Ws[i * NCLS + c];
    out[gid] = acc;
}

// ---------------- launch ---------------------------------------------
extern "C" void kernel_launch(void* const* d_in, const int* in_sizes, int n_in,
                              void* d_out, int out_size)
{
    const float* x  = (const float*)d_in[0];
    const void*  ei = d_in[1];
    const float* W1 = (const float*)d_in[2];
    const float* b1 = (const float*)d_in[3];
    const float* W2 = (const float*)d_in[4];
    const float* b2 = (const float*)d_in[5];
    const float* Wc = (const float*)d_in[6];
    const float* bc = (const float*)d_in[7];
    float* out = (float*)d_out;

    void* tmp;
    cudaGetSymbolAddress(&tmp, g_cnt);  int*    p_cnt  = (int*)tmp;
    cudaGetSymbolAddress(&tmp, g_fill); int*    p_fill = (int*)tmp;
    cudaGetSymbolAddress(&tmp, g_hop1); float4* p_hop1 = (float4*)tmp;
    cudaGetSymbolAddress(&tmp, g_hop2); float4* p_hop2 = (float4*)tmp;
    cudaGetSymbolAddress(&tmp, g_hop3); float4* p_hop3 = (float4*)tmp;
    cudaGetSymbolAddress(&tmp, g_h1);   float4* p_h1   = (float4*)tmp;
    cudaGetSymbolAddress(&tmp, g_h2);   float4* p_h2   = (float4*)tmp;

    cudaFuncSetAttribute(k_gemm_mma, cudaFuncAttributeMaxDynamicSharedMemorySize,
                         GEMM_SMEM);

    const int EB = (NE + 255) / 256;
    const int SB = (NN * 16 + 255) / 256;
    const int NB = (NN + 255) / 256;
    const int GB = (NN + 127) / 128;
    const int CB = (NN * NCLS + 255) / 256;

    // ---- CSR build ----
    k_detect<<<1, 32>>>((const long long*)ei);
    k_convert<<<EB, 256>>>(ei);
    cudaMemsetAsync(p_cnt, 0, NN * sizeof(int));
    cudaMemsetAsync(p_fill, 0, NN * sizeof(int));
    k_hist<<<EB, 256>>>();
    k_dinv<<<NB, 256>>>();
    k_scan1<<<SCAN_NB, 256>>>();
    k_scan2<<<1, 512>>>();
    k_scan3<<<SCAN_NB, 256>>>();
    k_fill<<<EB, 256>>>();

    // ---- layer 1 ----
    k_spmm_csr<<<SB, 256>>>((const float4*)x, p_hop1);
    k_spmm_csr<<<SB, 256>>>(p_hop1, p_hop2);
    k_spmm_csr<<<SB, 256>>>(p_hop2, p_hop3);
    k_gemm_mma<<<GB, 128, GEMM_SMEM>>>((const float4*)x, p_hop1, p_hop2, p_hop3,
                                       W1, b1, (float*)p_h1, 1);

    // ---- layer 2 ----
    k_spmm_csr<<<SB, 256>>>(p_h1, p_hop1);
    k_spmm_csr<<<SB, 256>>>(p_hop1, p_hop2);
    k_spmm_csr<<<SB, 256>>>(p_hop2, p_hop3);
    k_gemm_mma<<<GB, 128, GEMM_SMEM>>>(p_h1, p_hop1, p_hop2, p_hop3,
                                       W2, b2, (float*)p_h2, 1);

    // ---- classifier ----
    k_classifier<<<CB, 256>>>((const float*)p_h2, Wc, bc, out);
}